// round 6
// baseline (speedup 1.0000x reference)
#include <cuda_runtime.h>

// ---------------------------------------------------------------------------
// GATSummarizer: 4-layer GAT + mean pool + sigmoid head.
// CSR-by-dst build once per launch, then per layer:
//   tiled fp32 GEMM -> attention coefficients -> warp-per-node
//   segment-softmax + weighted gather (no atomics in the hot path).
// Index dtype (int32 vs int64) auto-detected on device (JAX x64-off trap).
// ---------------------------------------------------------------------------

#define NMAX 50016
#define ETMAX 860032
#define NGRAPH 64

// scratch (device globals: allocation-free per harness rules)
__device__ __align__(16) float g_h0[NMAX * 96];   // GEMM output (current h)
__device__ __align__(16) float g_h1[NMAX * 96];   // aggregated output
__device__ float g_es[NMAX * 2];
__device__ float g_ed[NMAX * 2];
__device__ float g_ebuf[ETMAX * 2];    // per-edge e / p values (CSR order)
__device__ int   g_cnt[NMAX];
__device__ int   g_rowptr[NMAX + 1];
__device__ int   g_cursor[NMAX];
__device__ int   g_csrc[ETMAX];
__device__ float g_psum[NGRAPH * 96];
__device__ float g_pcnt[NGRAPH];
__device__ int   g_is64_e;             // edge_index is int64?
__device__ int   g_is64_b;             // batch is int64?

// -------------------------- index dtype detection --------------------------
// int64 nonneg values < 2^31 stored little-endian: odd 32-bit words are 0.
__global__ void detect_k(const void* __restrict__ eidx,
                         const void* __restrict__ batch, int N) {
    if (threadIdx.x != 0 || blockIdx.x != 0) return;
    const int* e32 = (const int*)eidx;
    int all0 = 1;
    for (int i = 1; i < 64; i += 2) if (e32[i] != 0) all0 = 0;
    g_is64_e = all0;
    // batch: sorted, starts at 0 -> probe middle of the first N words
    // (values there are ~NGRAPH/2 != 0 for int32 layout).
    const int* b32 = (const int*)batch;
    int base = (N / 2) & ~1;           // even word index, < N words either way
    all0 = 1;
    for (int i = 1; i < 64; i += 2) if (b32[base + i] != 0) all0 = 0;
    g_is64_b = all0;
}

__device__ __forceinline__ int load_idx(const void* p, long long i, int is64) {
    return is64 ? (int)((const long long*)p)[i] : ((const int*)p)[i];
}

// ------------------------------- CSR build --------------------------------

__global__ void zero_cnt_k(int N) {
    int i = blockIdx.x * blockDim.x + threadIdx.x;
    if (i < N) g_cnt[i] = 0;
}

__global__ void count_k(const void* __restrict__ eidx, int E, int N) {
    int i = blockIdx.x * blockDim.x + threadIdx.x;
    int ET = E + N;
    if (i >= ET) return;
    int is64 = g_is64_e;
    int dst = (i < E) ? load_idx(eidx, (long long)E + i, is64) : (i - E);
    atomicAdd(&g_cnt[dst], 1);
}

// single-block hierarchical scan over N counts -> exclusive rowptr
__global__ void scan_k(int N) {
    __shared__ int warpsums[32];
    __shared__ int carry_sh;
    int t = threadIdx.x;
    if (t == 0) { carry_sh = 0; g_rowptr[0] = 0; }
    __syncthreads();
    for (int base = 0; base < N; base += 1024) {
        int i = base + t;
        int v = (i < N) ? g_cnt[i] : 0;
        int x = v;
        #pragma unroll
        for (int o = 1; o < 32; o <<= 1) {
            int y = __shfl_up_sync(0xffffffffu, x, o);
            if ((t & 31) >= o) x += y;
        }
        if ((t & 31) == 31) warpsums[t >> 5] = x;
        __syncthreads();
        if (t < 32) {
            int w = warpsums[t];
            #pragma unroll
            for (int o = 1; o < 32; o <<= 1) {
                int y = __shfl_up_sync(0xffffffffu, w, o);
                if (t >= o) w += y;
            }
            warpsums[t] = w;
        }
        __syncthreads();
        int incl = x + ((t >= 32) ? warpsums[(t >> 5) - 1] : 0);
        int total = warpsums[31];
        int c = carry_sh;
        if (i < N) g_rowptr[i + 1] = c + incl;
        __syncthreads();
        if (t == 0) carry_sh = c + total;
        __syncthreads();
    }
}

__global__ void cursor_k(int N) {
    int i = blockIdx.x * blockDim.x + threadIdx.x;
    if (i < N) g_cursor[i] = g_rowptr[i];
}

__global__ void fill_k(const void* __restrict__ eidx, int E, int N) {
    int i = blockIdx.x * blockDim.x + threadIdx.x;
    int ET = E + N;
    if (i >= ET) return;
    int is64 = g_is64_e;
    int src, dst;
    if (i < E) {
        src = load_idx(eidx, i, is64);
        dst = load_idx(eidx, (long long)E + i, is64);
    } else {
        src = dst = i - E;
    }
    int pos = atomicAdd(&g_cursor[dst], 1);
    g_csrc[pos] = src;
}

// ------------------------------- GEMM -------------------------------------
// C[N,96] = A[N,K] @ W[K,96].  BM=64, BN=96 (full width), BK=16, 4x6 microtile.
template <int K>
__global__ void __launch_bounds__(256) gemm_k(const float* __restrict__ Aext,
                                              int useExt,
                                              const float* __restrict__ W,
                                              int N) {
    const int BM = 64, BN = 96, BK = 16, TM = 4, TN = 6;
    __shared__ float As[BM][BK + 1];
    __shared__ float Bs[BK][BN];
    const float* A = useExt ? Aext : g_h1;
    float* C = g_h0;
    int tid = threadIdx.x;
    int tc = tid & 15;       // 0..15 (col groups of 6)
    int tr = tid >> 4;       // 0..15 (row groups of 4)
    int rowBase = blockIdx.x * BM;
    float acc[TM][TN];
    #pragma unroll
    for (int i = 0; i < TM; i++)
        #pragma unroll
        for (int j = 0; j < TN; j++) acc[i][j] = 0.0f;

    for (int k0 = 0; k0 < K; k0 += BK) {
        {
            int r = tid >> 2;           // 0..63
            int kk = (tid & 3) * 4;     // 0,4,8,12
            int grow = rowBase + r;
            float4 av = make_float4(0.f, 0.f, 0.f, 0.f);
            if (grow < N)
                av = *(const float4*)(A + (size_t)grow * K + k0 + kk);
            As[r][kk + 0] = av.x; As[r][kk + 1] = av.y;
            As[r][kk + 2] = av.z; As[r][kk + 3] = av.w;
        }
        for (int i = tid; i < BK * BN; i += 256) {
            int rr = i / BN, cc = i - rr * BN;
            Bs[rr][cc] = W[(size_t)(k0 + rr) * BN + cc];
        }
        __syncthreads();
        #pragma unroll
        for (int k = 0; k < BK; k++) {
            float a[TM], b[TN];
            #pragma unroll
            for (int i = 0; i < TM; i++) a[i] = As[tr * TM + i][k];
            #pragma unroll
            for (int j = 0; j < TN; j++) b[j] = Bs[k][tc * TN + j];
            #pragma unroll
            for (int i = 0; i < TM; i++)
                #pragma unroll
                for (int j = 0; j < TN; j++) acc[i][j] += a[i] * b[j];
        }
        __syncthreads();
    }
    #pragma unroll
    for (int i = 0; i < TM; i++) {
        int grow = rowBase + tr * TM + i;
        if (grow < N) {
            float* crow = C + (size_t)grow * 96 + tc * TN;
            #pragma unroll
            for (int j = 0; j < TN; j++) crow[j] = acc[i][j];
        }
    }
}

// -------------------- attention coefficients (es, ed) ----------------------
template <int H>
__global__ void attn_k(const float* __restrict__ as,
                       const float* __restrict__ ad, int N) {
    int warp = (blockIdx.x * blockDim.x + threadIdx.x) >> 5;
    int lane = threadIdx.x & 31;
    if (warp >= N) return;
    const float* hr = g_h0 + (size_t)warp * 96;
    float aS0 = 0.f, aS1 = 0.f, aD0 = 0.f, aD1 = 0.f;
    #pragma unroll
    for (int j = 0; j < 3; j++) {
        int c = lane + 32 * j;
        float hv = hr[c];
        float s = as[c] * hv;    // a_src flat: channel index
        float d = ad[c] * hv;
        if (H == 2 && c >= 48) { aS1 += s; aD1 += d; }
        else                   { aS0 += s; aD0 += d; }
    }
    #pragma unroll
    for (int o = 16; o; o >>= 1) {
        aS0 += __shfl_xor_sync(0xffffffffu, aS0, o);
        aD0 += __shfl_xor_sync(0xffffffffu, aD0, o);
        if (H == 2) {
            aS1 += __shfl_xor_sync(0xffffffffu, aS1, o);
            aD1 += __shfl_xor_sync(0xffffffffu, aD1, o);
        }
    }
    if (lane == 0) {
        if (H == 2) {
            g_es[warp * 2 + 0] = aS0; g_es[warp * 2 + 1] = aS1;
            g_ed[warp * 2 + 0] = aD0; g_ed[warp * 2 + 1] = aD1;
        } else {
            g_es[warp] = aS0; g_ed[warp] = aD0;
        }
    }
}

// ------------- segment softmax + weighted aggregation (warp/node) ----------
template <int H>
__global__ void agg_k(const float* __restrict__ bias, int N) {
    int v = (blockIdx.x * blockDim.x + threadIdx.x) >> 5;
    int lane = threadIdx.x & 31;
    if (v >= N) return;
    int beg = g_rowptr[v], end = g_rowptr[v + 1];

    float ed0 = g_ed[v * H];
    float ed1 = (H == 2) ? g_ed[v * 2 + 1] : 0.f;

    // phase A: e = leaky_relu(es[src] + ed[v]), store, track max
    float m0 = -3.4e38f, m1 = -3.4e38f;
    for (int i = beg + lane; i < end; i += 32) {
        int s = g_csrc[i];
        float e0 = g_es[s * H] + ed0;
        e0 = (e0 > 0.f) ? e0 : 0.2f * e0;
        g_ebuf[i * H] = e0;
        m0 = fmaxf(m0, e0);
        if (H == 2) {
            float e1 = g_es[s * 2 + 1] + ed1;
            e1 = (e1 > 0.f) ? e1 : 0.2f * e1;
            g_ebuf[i * 2 + 1] = e1;
            m1 = fmaxf(m1, e1);
        }
    }
    #pragma unroll
    for (int o = 16; o; o >>= 1) {
        m0 = fmaxf(m0, __shfl_xor_sync(0xffffffffu, m0, o));
        if (H == 2) m1 = fmaxf(m1, __shfl_xor_sync(0xffffffffu, m1, o));
    }

    // phase B: p = exp(e - m), store, sum
    float s0 = 0.f, s1 = 0.f;
    for (int i = beg + lane; i < end; i += 32) {
        float p0 = __expf(g_ebuf[i * H] - m0);
        g_ebuf[i * H] = p0;
        s0 += p0;
        if (H == 2) {
            float p1 = __expf(g_ebuf[i * 2 + 1] - m1);
            g_ebuf[i * 2 + 1] = p1;
            s1 += p1;
        }
    }
    #pragma unroll
    for (int o = 16; o; o >>= 1) {
        s0 += __shfl_xor_sync(0xffffffffu, s0, o);
        if (H == 2) s1 += __shfl_xor_sync(0xffffffffu, s1, o);
    }
    float inv0 = 1.0f / s0;
    float inv1 = (H == 2) ? 1.0f / s1 : inv0;

    // phase C: lanes over channels (c, c+32, c+64); edges sequential
    float a0 = 0.f, a1 = 0.f, a2 = 0.f;
    int c0 = lane, c1 = lane + 32, c2 = lane + 64;
    for (int i = beg; i < end; i++) {
        int s = g_csrc[i];                       // warp-broadcast load
        const float* hr = g_h0 + (size_t)s * 96;
        if (H == 2) {
            float p0 = g_ebuf[i * 2 + 0];
            float p1 = g_ebuf[i * 2 + 1];
            a0 += p0 * hr[c0];                   // c0 in [0,32) -> head 0
            a1 += ((c1 < 48) ? p0 : p1) * hr[c1];
            a2 += p1 * hr[c2];                   // c2 in [64,96) -> head 1
        } else {
            float p = g_ebuf[i];
            a0 += p * hr[c0];
            a1 += p * hr[c1];
            a2 += p * hr[c2];
        }
    }
    float o0, o1, o2;
    if (H == 2) {
        o0 = a0 * inv0 + bias[c0];
        o1 = a1 * ((c1 < 48) ? inv0 : inv1) + bias[c1];
        o2 = a2 * inv1 + bias[c2];
    } else {
        o0 = a0 * inv0 + bias[c0];
        o1 = a1 * inv0 + bias[c1];
        o2 = a2 * inv0 + bias[c2];
    }
    float* orow = g_h1 + (size_t)v * 96;
    orow[c0] = fmaxf(o0, 0.f);   // relu
    orow[c1] = fmaxf(o1, 0.f);
    orow[c2] = fmaxf(o2, 0.f);
}

// ------------------------------- pooling ----------------------------------
__global__ void zero_pool_k() {
    for (int i = threadIdx.x; i < NGRAPH * 96; i += blockDim.x) g_psum[i] = 0.f;
    if (threadIdx.x < NGRAPH) g_pcnt[threadIdx.x] = 0.f;
}

__global__ void pool_k(const void* __restrict__ batch, int N) {
    int v = (blockIdx.x * blockDim.x + threadIdx.x) >> 5;
    int lane = threadIdx.x & 31;
    if (v >= N) return;
    int g = load_idx(batch, v, g_is64_b);
    const float* hr = g_h1 + (size_t)v * 96;
    atomicAdd(&g_psum[g * 96 + lane],      hr[lane]);
    atomicAdd(&g_psum[g * 96 + lane + 32], hr[lane + 32]);
    atomicAdd(&g_psum[g * 96 + lane + 64], hr[lane + 64]);
    if (lane == 0) atomicAdd(&g_pcnt[g], 1.0f);
}

__global__ void head_k(const float* __restrict__ Wc,
                       const float* __restrict__ bc,
                       float* __restrict__ out) {
    int g = (blockIdx.x * blockDim.x + threadIdx.x) >> 5;
    int lane = threadIdx.x & 31;
    if (g >= NGRAPH) return;
    float cnt = fmaxf(g_pcnt[g], 1.0f);
    float acc = 0.f;
    #pragma unroll
    for (int j = 0; j < 3; j++) {
        int c = lane + 32 * j;
        acc += (g_psum[g * 96 + c] / cnt) * Wc[c];
    }
    #pragma unroll
    for (int o = 16; o; o >>= 1)
        acc += __shfl_xor_sync(0xffffffffu, acc, o);
    if (lane == 0)
        out[g] = 1.0f / (1.0f + __expf(-(acc + bc[0])));
}

// ------------------------------- launch -----------------------------------
extern "C" void kernel_launch(void* const* d_in, const int* in_sizes, int n_in,
                              void* d_out, int out_size) {
    const float* x     = (const float*)d_in[0];
    const void*  eidx  = d_in[1];            // int32 or int64 (auto-detected)
    // d_in[2] edge_weight: ignored by GATConv (edge_dim=None)
    const void*  batch = d_in[3];
    const float* W1  = (const float*)d_in[4];
    const float* as1 = (const float*)d_in[5];
    const float* ad1 = (const float*)d_in[6];
    const float* b1  = (const float*)d_in[7];
    const float* W2  = (const float*)d_in[8];
    const float* as2 = (const float*)d_in[9];
    const float* ad2 = (const float*)d_in[10];
    const float* b2  = (const float*)d_in[11];
    const float* W3  = (const float*)d_in[12];
    const float* as3 = (const float*)d_in[13];
    const float* ad3 = (const float*)d_in[14];
    const float* b3  = (const float*)d_in[15];
    const float* W4  = (const float*)d_in[16];
    const float* as4 = (const float*)d_in[17];
    const float* ad4 = (const float*)d_in[18];
    const float* b4  = (const float*)d_in[19];
    const float* Wc  = (const float*)d_in[20];
    const float* bc  = (const float*)d_in[21];
    float* out = (float*)d_out;

    int N  = in_sizes[3];          // 50000 (batch element count)
    int E  = in_sizes[2];          // 800000 (edge_weight element count)
    int ET = E + N;

    detect_k<<<1, 32>>>(eidx, batch, N);

    // CSR build
    zero_cnt_k<<<(N + 255) / 256, 256>>>(N);
    count_k<<<(ET + 255) / 256, 256>>>(eidx, E, N);
    scan_k<<<1, 1024>>>(N);
    cursor_k<<<(N + 255) / 256, 256>>>(N);
    fill_k<<<(ET + 255) / 256, 256>>>(eidx, E, N);

    int gb = (N + 63) / 64;
    int wgrid = (int)(((long long)N * 32 + 255) / 256);

    // layer 1 (H=2, C=48)
    gemm_k<128><<<gb, 256>>>(x, 1, W1, N);
    attn_k<2><<<wgrid, 256>>>(as1, ad1, N);
    agg_k<2><<<wgrid, 256>>>(b1, N);
    // layer 2 (H=1, C=96)
    gemm_k<96><<<gb, 256>>>(nullptr, 0, W2, N);
    attn_k<1><<<wgrid, 256>>>(as2, ad2, N);
    agg_k<1><<<wgrid, 256>>>(b2, N);
    // layer 3
    gemm_k<96><<<gb, 256>>>(nullptr, 0, W3, N);
    attn_k<1><<<wgrid, 256>>>(as3, ad3, N);
    agg_k<1><<<wgrid, 256>>>(b3, N);
    // layer 4
    gemm_k<96><<<gb, 256>>>(nullptr, 0, W4, N);
    attn_k<1><<<wgrid, 256>>>(as4, ad4, N);
    agg_k<1><<<wgrid, 256>>>(b4, N);

    // mean pool + head
    zero_pool_k<<<1, 1024>>>();
    pool_k<<<wgrid, 256>>>(batch, N);
    head_k<<<2, 1024>>>(Wc, bc, out);
}

// round 8
// speedup vs baseline: 1.2897x; 1.2897x over previous
#include <cuda_runtime.h>

// ---------------------------------------------------------------------------
// GATSummarizer: 4-layer GAT + mean pool + sigmoid head.
// R3: multi-block scan, attn fused into GEMM epilogue, register fast path
// for degree<=32 in aggregation, 128x96 GEMM tiles with 8x6 microtile.
// ---------------------------------------------------------------------------

#define NMAX 50016
#define ETMAX 860032
#define NGRAPH 64

__device__ __align__(16) float g_h0[NMAX * 96];   // GEMM output (current h)
__device__ __align__(16) float g_h1[NMAX * 96];   // aggregated output
__device__ float g_es[NMAX * 2];
__device__ float g_ed[NMAX * 2];
__device__ float g_ebuf[ETMAX * 2];    // slow-path per-edge values
__device__ int   g_cnt[NMAX];
__device__ int   g_stmp[NMAX];         // per-element inclusive scan (pre-offset)
__device__ int   g_bsum[256];          // per-block sums
__device__ int   g_rowptr[NMAX + 1];
__device__ int   g_cursor[NMAX];
__device__ int   g_csrc[ETMAX];
__device__ float g_psum[NGRAPH * 96];
__device__ float g_pcnt[NGRAPH];
__device__ int   g_is64_e;
__device__ int   g_is64_b;

// ---------------- init: zero counters/pools + dtype probe ------------------
__global__ void init_k(const void* __restrict__ eidx,
                       const void* __restrict__ batch, int N) {
    int i = blockIdx.x * blockDim.x + threadIdx.x;
    if (i < N) g_cnt[i] = 0;
    if (i < NGRAPH * 96) g_psum[i] = 0.f;
    if (i < NGRAPH) g_pcnt[i] = 0.f;
    if (i == 0) {
        // int64 nonneg < 2^31 little-endian: odd 32-bit words are zero.
        const int* e32 = (const int*)eidx;
        int all0 = 1;
        for (int j = 1; j < 64; j += 2) if (e32[j] != 0) all0 = 0;
        g_is64_e = all0;
        const int* b32 = (const int*)batch;
        int base = (N / 2) & ~1;
        all0 = 1;
        for (int j = 1; j < 64; j += 2) if (b32[base + j] != 0) all0 = 0;
        g_is64_b = all0;
    }
}

__device__ __forceinline__ int load_idx(const void* p, long long i, int is64) {
    return is64 ? (int)((const long long*)p)[i] : ((const int*)p)[i];
}

// ------------------------------- CSR build --------------------------------
__global__ void count_k(const void* __restrict__ eidx, int E, int N) {
    int i = blockIdx.x * blockDim.x + threadIdx.x;
    int ET = E + N;
    if (i >= ET) return;
    int is64 = g_is64_e;
    int dst = (i < E) ? load_idx(eidx, (long long)E + i, is64) : (i - E);
    atomicAdd(&g_cnt[dst], 1);
}

// per-256-block inclusive scan of g_cnt -> g_stmp, block totals -> g_bsum
__global__ void scanA_k(int N) {
    __shared__ int ws[8];
    int tid = threadIdx.x;
    int i = blockIdx.x * 256 + tid;
    int lane = tid & 31, warp = tid >> 5;
    int v = (i < N) ? g_cnt[i] : 0;
    int x = v;
    #pragma unroll
    for (int o = 1; o < 32; o <<= 1) {
        int y = __shfl_up_sync(0xffffffffu, x, o);
        if (lane >= o) x += y;
    }
    if (lane == 31) ws[warp] = x;
    __syncthreads();
    if (tid == 0) {
        int run = 0;
        #pragma unroll
        for (int w = 0; w < 8; w++) { int t = ws[w]; ws[w] = run; run += t; }
    }
    __syncthreads();
    int incl = x + ws[warp];
    if (i < N) g_stmp[i] = incl;
    if (tid == 255) g_bsum[blockIdx.x] = incl;
}

// single tiny block: inclusive scan of block sums in place
__global__ void scanB_k(int nb) {
    __shared__ int ws[8];
    int tid = threadIdx.x;
    int lane = tid & 31, warp = tid >> 5;
    int v = (tid < nb) ? g_bsum[tid] : 0;
    int x = v;
    #pragma unroll
    for (int o = 1; o < 32; o <<= 1) {
        int y = __shfl_up_sync(0xffffffffu, x, o);
        if (lane >= o) x += y;
    }
    if (lane == 31) ws[warp] = x;
    __syncthreads();
    if (tid == 0) {
        int run = 0;
        #pragma unroll
        for (int w = 0; w < 8; w++) { int t = ws[w]; ws[w] = run; run += t; }
    }
    __syncthreads();
    if (tid < nb) g_bsum[tid] = x + ws[warp];
}

// add block offsets -> rowptr (exclusive at [i], inclusive at [i+1]) + cursor
__global__ void scanC_k(int N) {
    int i = blockIdx.x * 256 + threadIdx.x;
    if (i >= N) return;
    int off = blockIdx.x ? g_bsum[blockIdx.x - 1] : 0;
    int incl = g_stmp[i] + off;
    g_rowptr[i + 1] = incl;
    g_cursor[i] = incl - g_cnt[i];
    if (i == 0) g_rowptr[0] = 0;
}

__global__ void fill_k(const void* __restrict__ eidx, int E, int N) {
    int i = blockIdx.x * blockDim.x + threadIdx.x;
    int ET = E + N;
    if (i >= ET) return;
    int is64 = g_is64_e;
    int src, dst;
    if (i < E) {
        src = load_idx(eidx, i, is64);
        dst = load_idx(eidx, (long long)E + i, is64);
    } else {
        src = dst = i - E;
    }
    int pos = atomicAdd(&g_cursor[dst], 1);
    g_csrc[pos] = src;
}

// --------------------- GEMM + fused attention epilogue ---------------------
// C[N,96] = A[N,K] @ W[K,96]; then es/ed per row via shfl reduction.
// BM=128, BN=96 (full width), BK=16, microtile 8x6, 256 threads.
template <int K, int H>
__global__ void __launch_bounds__(256) gemm_attn_k(const float* __restrict__ Aext,
                                                   int useExt,
                                                   const float* __restrict__ W,
                                                   const float* __restrict__ as,
                                                   const float* __restrict__ ad,
                                                   int N) {
    const int BM = 128, BN = 96, BK = 16, TM = 8, TN = 6;
    __shared__ float As[BM][BK + 1];
    __shared__ float Bs[BK][BN];
    const float* A = useExt ? Aext : g_h1;
    int tid = threadIdx.x;
    int tc = tid & 15;        // 0..15 -> col group of 6
    int tr = tid >> 4;        // 0..15 -> row group of 8
    int rowBase = blockIdx.x * BM;
    float acc[TM][TN];
    #pragma unroll
    for (int i = 0; i < TM; i++)
        #pragma unroll
        for (int j = 0; j < TN; j++) acc[i][j] = 0.0f;

    for (int k0 = 0; k0 < K; k0 += BK) {
        #pragma unroll
        for (int l = 0; l < 2; l++) {
            int lin = tid * 2 + l;            // 0..511
            int r = lin >> 2;                 // 0..127
            int kk = (lin & 3) * 4;           // 0,4,8,12
            int grow = rowBase + r;
            float4 av = make_float4(0.f, 0.f, 0.f, 0.f);
            if (grow < N)
                av = *(const float4*)(A + (size_t)grow * K + k0 + kk);
            As[r][kk + 0] = av.x; As[r][kk + 1] = av.y;
            As[r][kk + 2] = av.z; As[r][kk + 3] = av.w;
        }
        #pragma unroll
        for (int l = 0; l < 6; l++) {
            int i = tid + l * 256;            // 0..1535
            int rr = i / BN, cc = i - rr * BN;
            Bs[rr][cc] = W[(size_t)(k0 + rr) * BN + cc];
        }
        __syncthreads();
        #pragma unroll
        for (int k = 0; k < BK; k++) {
            float a[TM], b[TN];
            #pragma unroll
            for (int i = 0; i < TM; i++) a[i] = As[tr * TM + i][k];
            #pragma unroll
            for (int j = 0; j < TN; j++) b[j] = Bs[k][tc * TN + j];
            #pragma unroll
            for (int i = 0; i < TM; i++)
                #pragma unroll
                for (int j = 0; j < TN; j++) acc[i][j] += a[i] * b[j];
        }
        __syncthreads();
    }

    // epilogue: write C and fused es/ed
    float asv[TN], adv[TN];
    #pragma unroll
    for (int j = 0; j < TN; j++) { asv[j] = as[tc * TN + j]; adv[j] = ad[tc * TN + j]; }

    #pragma unroll
    for (int i = 0; i < TM; i++) {
        int grow = rowBase + tr * TM + i;
        float es = 0.f, ed = 0.f;
        #pragma unroll
        for (int j = 0; j < TN; j++) { es += asv[j] * acc[i][j]; ed += adv[j] * acc[i][j]; }
        // reduce across the 16 tc-lanes that share this row.
        // lane = (tr&1)*16 + tc, so xor offsets stay within the right subset.
        if (H == 2) {
            // head boundary at col 48 = tc 8: reduce within 8-lane halves
            #pragma unroll
            for (int o = 1; o < 8; o <<= 1) {
                es += __shfl_xor_sync(0xffffffffu, es, o);
                ed += __shfl_xor_sync(0xffffffffu, ed, o);
            }
        } else {
            #pragma unroll
            for (int o = 1; o < 16; o <<= 1) {
                es += __shfl_xor_sync(0xffffffffu, es, o);
                ed += __shfl_xor_sync(0xffffffffu, ed, o);
            }
        }
        if (grow < N) {
            float* crow = g_h0 + (size_t)grow * 96 + tc * TN;
            #pragma unroll
            for (int j = 0; j < TN; j++) crow[j] = acc[i][j];
            if (H == 2) {
                if (tc == 0) { g_es[grow * 2 + 0] = es; g_ed[grow * 2 + 0] = ed; }
                if (tc == 8) { g_es[grow * 2 + 1] = es; g_ed[grow * 2 + 1] = ed; }
            } else {
                if (tc == 0) { g_es[grow] = es; g_ed[grow] = ed; }
            }
        }
    }
}

// ------------- segment softmax + weighted aggregation (warp/node) ----------
template <int H>
__global__ void agg_k(const float* __restrict__ bias, int N) {
    int v = (blockIdx.x * blockDim.x + threadIdx.x) >> 5;
    int lane = threadIdx.x & 31;
    if (v >= N) return;
    int beg = g_rowptr[v], end = g_rowptr[v + 1];
    int deg = end - beg;

    float ed0 = g_ed[v * H];
    float ed1 = (H == 2) ? g_ed[v * 2 + 1] : 0.f;

    float inv0, inv1;
    float a0 = 0.f, a1 = 0.f, a2 = 0.f;
    int c0 = lane, c1 = lane + 32, c2 = lane + 64;

    if (deg <= 32) {
        // ---------- fast path: one edge per lane, all in registers ----------
        int s = (lane < deg) ? g_csrc[beg + lane] : 0;
        float e0 = -3.4e38f, e1 = -3.4e38f;
        if (lane < deg) {
            e0 = g_es[s * H] + ed0;
            e0 = (e0 > 0.f) ? e0 : 0.2f * e0;
            if (H == 2) {
                e1 = g_es[s * 2 + 1] + ed1;
                e1 = (e1 > 0.f) ? e1 : 0.2f * e1;
            }
        }
        float m0 = e0, m1 = e1;
        #pragma unroll
        for (int o = 16; o; o >>= 1) {
            m0 = fmaxf(m0, __shfl_xor_sync(0xffffffffu, m0, o));
            if (H == 2) m1 = fmaxf(m1, __shfl_xor_sync(0xffffffffu, m1, o));
        }
        float p0 = (lane < deg) ? __expf(e0 - m0) : 0.f;
        float p1 = (H == 2 && lane < deg) ? __expf(e1 - m1) : 0.f;
        float s0 = p0, s1 = p1;
        #pragma unroll
        for (int o = 16; o; o >>= 1) {
            s0 += __shfl_xor_sync(0xffffffffu, s0, o);
            if (H == 2) s1 += __shfl_xor_sync(0xffffffffu, s1, o);
        }
        inv0 = 1.0f / s0;
        inv1 = (H == 2) ? 1.0f / s1 : inv0;

        for (int i = 0; i < deg; i++) {
            int si = __shfl_sync(0xffffffffu, s, i);
            float pi0 = __shfl_sync(0xffffffffu, p0, i);
            const float* hr = g_h0 + (size_t)si * 96;
            if (H == 2) {
                float pi1 = __shfl_sync(0xffffffffu, p1, i);
                a0 += pi0 * hr[c0];
                a1 += ((c1 < 48) ? pi0 : pi1) * hr[c1];
                a2 += pi1 * hr[c2];
            } else {
                a0 += pi0 * hr[c0];
                a1 += pi0 * hr[c1];
                a2 += pi0 * hr[c2];
            }
        }
    } else {
        // ---------- slow path (rare): spill e/p to g_ebuf ----------
        float m0 = -3.4e38f, m1 = -3.4e38f;
        for (int i = beg + lane; i < end; i += 32) {
            int s = g_csrc[i];
            float e0 = g_es[s * H] + ed0;
            e0 = (e0 > 0.f) ? e0 : 0.2f * e0;
            g_ebuf[i * H] = e0;
            m0 = fmaxf(m0, e0);
            if (H == 2) {
                float e1 = g_es[s * 2 + 1] + ed1;
                e1 = (e1 > 0.f) ? e1 : 0.2f * e1;
                g_ebuf[i * 2 + 1] = e1;
                m1 = fmaxf(m1, e1);
            }
        }
        #pragma unroll
        for (int o = 16; o; o >>= 1) {
            m0 = fmaxf(m0, __shfl_xor_sync(0xffffffffu, m0, o));
            if (H == 2) m1 = fmaxf(m1, __shfl_xor_sync(0xffffffffu, m1, o));
        }
        float s0 = 0.f, s1 = 0.f;
        for (int i = beg + lane; i < end; i += 32) {
            float p0 = __expf(g_ebuf[i * H] - m0);
            g_ebuf[i * H] = p0;
            s0 += p0;
            if (H == 2) {
                float p1 = __expf(g_ebuf[i * 2 + 1] - m1);
                g_ebuf[i * 2 + 1] = p1;
                s1 += p1;
            }
        }
        #pragma unroll
        for (int o = 16; o; o >>= 1) {
            s0 += __shfl_xor_sync(0xffffffffu, s0, o);
            if (H == 2) s1 += __shfl_xor_sync(0xffffffffu, s1, o);
        }
        inv0 = 1.0f / s0;
        inv1 = (H == 2) ? 1.0f / s1 : inv0;

        for (int i = beg; i < end; i++) {
            int s = g_csrc[i];
            const float* hr = g_h0 + (size_t)s * 96;
            if (H == 2) {
                float p0 = g_ebuf[i * 2 + 0];
                float p1 = g_ebuf[i * 2 + 1];
                a0 += p0 * hr[c0];
                a1 += ((c1 < 48) ? p0 : p1) * hr[c1];
                a2 += p1 * hr[c2];
            } else {
                float p = g_ebuf[i];
                a0 += p * hr[c0];
                a1 += p * hr[c1];
                a2 += p * hr[c2];
            }
        }
    }

    float o0, o1, o2;
    if (H == 2) {
        o0 = a0 * inv0 + bias[c0];
        o1 = a1 * ((c1 < 48) ? inv0 : inv1) + bias[c1];
        o2 = a2 * inv1 + bias[c2];
    } else {
        o0 = a0 * inv0 + bias[c0];
        o1 = a1 * inv0 + bias[c1];
        o2 = a2 * inv0 + bias[c2];
    }
    float* orow = g_h1 + (size_t)v * 96;
    orow[c0] = fmaxf(o0, 0.f);
    orow[c1] = fmaxf(o1, 0.f);
    orow[c2] = fmaxf(o2, 0.f);
}

// ------------------------------- pooling ----------------------------------
__global__ void pool_k(const void* __restrict__ batch, int N) {
    int v = (blockIdx.x * blockDim.x + threadIdx.x) >> 5;
    int lane = threadIdx.x & 31;
    if (v >= N) return;
    int g = load_idx(batch, v, g_is64_b);
    const float* hr = g_h1 + (size_t)v * 96;
    atomicAdd(&g_psum[g * 96 + lane],      hr[lane]);
    atomicAdd(&g_psum[g * 96 + lane + 32], hr[lane + 32]);
    atomicAdd(&g_psum[g * 96 + lane + 64], hr[lane + 64]);
    if (lane == 0) atomicAdd(&g_pcnt[g], 1.0f);
}

__global__ void head_k(const float* __restrict__ Wc,
                       const float* __restrict__ bc,
                       float* __restrict__ out) {
    int g = (blockIdx.x * blockDim.x + threadIdx.x) >> 5;
    int lane = threadIdx.x & 31;
    if (g >= NGRAPH) return;
    float cnt = fmaxf(g_pcnt[g], 1.0f);
    float acc = 0.f;
    #pragma unroll
    for (int j = 0; j < 3; j++) {
        int c = lane + 32 * j;
        acc += (g_psum[g * 96 + c] / cnt) * Wc[c];
    }
    #pragma unroll
    for (int o = 16; o; o >>= 1)
        acc += __shfl_xor_sync(0xffffffffu, acc, o);
    if (lane == 0)
        out[g] = 1.0f / (1.0f + __expf(-(acc + bc[0])));
}

// ------------------------------- launch -----------------------------------
extern "C" void kernel_launch(void* const* d_in, const int* in_sizes, int n_in,
                              void* d_out, int out_size) {
    const float* x     = (const float*)d_in[0];
    const void*  eidx  = d_in[1];            // int32 or int64 (auto-detected)
    // d_in[2] edge_weight: ignored by GATConv (edge_dim=None)
    const void*  batch = d_in[3];
    const float* W1  = (const float*)d_in[4];
    const float* as1 = (const float*)d_in[5];
    const float* ad1 = (const float*)d_in[6];
    const float* b1  = (const float*)d_in[7];
    const float* W2  = (const float*)d_in[8];
    const float* as2 = (const float*)d_in[9];
    const float* ad2 = (const float*)d_in[10];
    const float* b2  = (const float*)d_in[11];
    const float* W3  = (const float*)d_in[12];
    const float* as3 = (const float*)d_in[13];
    const float* ad3 = (const float*)d_in[14];
    const float* b3  = (const float*)d_in[15];
    const float* W4  = (const float*)d_in[16];
    const float* as4 = (const float*)d_in[17];
    const float* ad4 = (const float*)d_in[18];
    const float* b4  = (const float*)d_in[19];
    const float* Wc  = (const float*)d_in[20];
    const float* bc  = (const float*)d_in[21];
    float* out = (float*)d_out;

    int N  = in_sizes[3];          // 50000
    int E  = in_sizes[2];          // 800000
    int ET = E + N;
    int nb = (N + 255) / 256;      // scan blocks (196)

    init_k<<<(N + 255) / 256, 256>>>(eidx, batch, N);
    count_k<<<(ET + 255) / 256, 256>>>(eidx, E, N);
    scanA_k<<<nb, 256>>>(N);
    scanB_k<<<1, 256>>>(nb);
    scanC_k<<<nb, 256>>>(N);
    fill_k<<<(ET + 255) / 256, 256>>>(eidx, E, N);

    int gb = (N + 127) / 128;
    int wgrid = (int)(((long long)N * 32 + 255) / 256);

    gemm_attn_k<128, 2><<<gb, 256>>>(x, 1, W1, as1, ad1, N);
    agg_k<2><<<wgrid, 256>>>(b1, N);
    gemm_attn_k<96, 1><<<gb, 256>>>(nullptr, 0, W2, as2, ad2, N);
    agg_k<1><<<wgrid, 256>>>(b2, N);
    gemm_attn_k<96, 1><<<gb, 256>>>(nullptr, 0, W3, as3, ad3, N);
    agg_k<1><<<wgrid, 256>>>(b3, N);
    gemm_attn_k<96, 1><<<gb, 256>>>(nullptr, 0, W4, as4, ad4, N);
    agg_k<1><<<wgrid, 256>>>(b4, N);

    pool_k<<<wgrid, 256>>>(batch, N);
    head_k<<<2, 1024>>>(Wc, bc, out);
}

// round 11
// speedup vs baseline: 1.4188x; 1.1001x over previous
#include <cuda_runtime.h>

// ---------------------------------------------------------------------------
// GATSummarizer: 4-layer GAT + mean pool + sigmoid head.
// R5: tensor-core GEMM via m16n8k8 TF32 hi/lo 3-term split (accuracy fix for
// R4's bf16 split), fused attn epilogue, single-pass arrival-order scan,
// pool fused into last aggregation.
// ---------------------------------------------------------------------------

#define NMAX 50016
#define ETMAX 860032
#define NGRAPH 64

__device__ __align__(16) float g_h0[NMAX * 96];   // GEMM output (current h)
__device__ __align__(16) float g_h1[NMAX * 96];   // aggregated output
__device__ float g_es[NMAX * 2];
__device__ float g_ed[NMAX * 2];
__device__ float g_ebuf[ETMAX * 2];    // slow-path per-edge values
__device__ int   g_cnt[NMAX];
__device__ int   g_begin[NMAX];        // CSR segment start per node
__device__ int   g_cursor[NMAX];
__device__ int   g_csrc[ETMAX];
__device__ int   g_total;
__device__ float g_psum[NGRAPH * 96];
__device__ float g_pcnt[NGRAPH];
__device__ int   g_is64_e;
__device__ int   g_is64_b;
// pre-packed W fragments: [layer][ks<=16][nt=12][lane=32][2 regs], tf32 bits
__device__ unsigned g_wp_hi[4 * 16 * 12 * 32 * 2];
__device__ unsigned g_wp_lo[4 * 16 * 12 * 32 * 2];

// ---------------- tf32 split helpers ----------------
__device__ __forceinline__ void split_tf32(float v, unsigned& hi, unsigned& lo) {
    unsigned h;
    asm("cvt.rna.tf32.f32 %0, %1;" : "=r"(h) : "f"(v));
    float r = v - __uint_as_float(h);
    asm("cvt.rna.tf32.f32 %0, %1;" : "=r"(lo) : "f"(r));
    hi = h;
}

__device__ __forceinline__ void mma_tf32(float* d,
                                         unsigned a0, unsigned a1,
                                         unsigned a2, unsigned a3,
                                         unsigned b0, unsigned b1) {
    asm volatile(
        "mma.sync.aligned.m16n8k8.row.col.f32.tf32.tf32.f32 "
        "{%0,%1,%2,%3},{%4,%5,%6,%7},{%8,%9},{%0,%1,%2,%3};"
        : "+f"(d[0]), "+f"(d[1]), "+f"(d[2]), "+f"(d[3])
        : "r"(a0), "r"(a1), "r"(a2), "r"(a3), "r"(b0), "r"(b1));
}

// ---------------- init: zero counters/pools + dtype probe ------------------
__global__ void init_k(const void* __restrict__ eidx,
                       const void* __restrict__ batch, int N) {
    int i = blockIdx.x * blockDim.x + threadIdx.x;
    if (i < N) g_cnt[i] = 0;
    if (i < NGRAPH * 96) g_psum[i] = 0.f;
    if (i < NGRAPH) g_pcnt[i] = 0.f;
    if (i == 0) {
        g_total = 0;
        const int* e32 = (const int*)eidx;
        int all0 = 1;
        for (int j = 1; j < 64; j += 2) if (e32[j] != 0) all0 = 0;
        g_is64_e = all0;
        const int* b32 = (const int*)batch;
        int base = (N / 2) & ~1;
        all0 = 1;
        for (int j = 1; j < 64; j += 2) if (b32[base + j] != 0) all0 = 0;
        g_is64_b = all0;
    }
}

__device__ __forceinline__ int load_idx(const void* p, long long i, int is64) {
    return is64 ? (int)((const long long*)p)[i] : ((const int*)p)[i];
}

// ------------------------------- CSR build --------------------------------
__global__ void count_k(const void* __restrict__ eidx, int E, int N) {
    int i = blockIdx.x * blockDim.x + threadIdx.x;
    int ET = E + N;
    if (i >= ET) return;
    int is64 = g_is64_e;
    int dst = (i < E) ? load_idx(eidx, (long long)E + i, is64) : (i - E);
    atomicAdd(&g_cnt[dst], 1);
}

// single-pass scan: block-local scan + arrival-order block offset.
// Segment placement is arbitrary but disjoint -> CSR stays valid.
__global__ void scan_k(int N) {
    __shared__ int ws[8];
    __shared__ int sh_off;
    int tid = threadIdx.x;
    int i = blockIdx.x * 256 + tid;
    int lane = tid & 31, warp = tid >> 5;
    int v = (i < N) ? g_cnt[i] : 0;
    int x = v;
    #pragma unroll
    for (int o = 1; o < 32; o <<= 1) {
        int y = __shfl_up_sync(0xffffffffu, x, o);
        if (lane >= o) x += y;
    }
    if (lane == 31) ws[warp] = x;
    __syncthreads();
    if (tid == 0) {
        int run = 0;
        #pragma unroll
        for (int w = 0; w < 8; w++) { int t = ws[w]; ws[w] = run; run += t; }
    }
    __syncthreads();
    int incl = x + ws[warp];
    if (tid == 255) sh_off = atomicAdd(&g_total, incl);
    __syncthreads();
    if (i < N) {
        int beg = sh_off + incl - v;
        g_begin[i] = beg;
        g_cursor[i] = beg;
    }
}

__global__ void fill_k(const void* __restrict__ eidx, int E, int N) {
    int i = blockIdx.x * blockDim.x + threadIdx.x;
    int ET = E + N;
    if (i >= ET) return;
    int is64 = g_is64_e;
    int src, dst;
    if (i < E) {
        src = load_idx(eidx, i, is64);
        dst = load_idx(eidx, (long long)E + i, is64);
    } else {
        src = dst = i - E;
    }
    int pos = atomicAdd(&g_cursor[dst], 1);
    g_csrc[pos] = src;
}

// ---------------- W fragment prep (all 4 layers, one launch) ---------------
// m16n8k8 B frag (col-major k8 x n8): b0 row=tg, col=g; b1 row=tg+4, col=g.
__global__ void wprep_k(const float* __restrict__ W1, const float* __restrict__ W2,
                        const float* __restrict__ W3, const float* __restrict__ W4) {
    int b = blockIdx.x;           // 52 blocks: ks-major across layers {16,12,12,12}
    int layer, ks;
    const float* W;
    if (b < 16)      { layer = 0; ks = b;      W = W1; }
    else if (b < 28) { layer = 1; ks = b - 16; W = W2; }
    else if (b < 40) { layer = 2; ks = b - 28; W = W3; }
    else             { layer = 3; ks = b - 40; W = W4; }
    int tid = threadIdx.x;        // 768 = 12 nt * 32 lanes * 2 regs
    int nt = tid / 64;
    int rem = tid % 64;
    int lane = rem >> 1;
    int reg = rem & 1;
    int tg = lane & 3, g = lane >> 2;
    int krow = ks * 8 + tg + reg * 4;
    int col = nt * 8 + g;
    float v = W[(size_t)krow * 96 + col];
    unsigned hi, lo;
    split_tf32(v, hi, lo);
    int idx = layer * 12288 + (ks * 12 + nt) * 64 + lane * 2 + reg;
    g_wp_hi[idx] = hi;
    g_wp_lo[idx] = lo;
}

// --------------- tensor-core GEMM + fused attention epilogue ---------------
// C[N,96] = A[N,K] @ W[K,96] via m16n8k8 tf32 mma, hi/lo 3-term split.
// 256 threads = 8 warps; warp owns 16 rows x 96 cols. A split on the fly.
template <int K, int H>
__global__ void __launch_bounds__(256) mma_gemm_attn_k(
    const float* __restrict__ Aext, int useExt, int layer,
    const float* __restrict__ as, const float* __restrict__ ad, int N) {
    const float* A = useExt ? Aext : g_h1;
    int lane = threadIdx.x & 31, warp = threadIdx.x >> 5;
    int g = lane >> 2, tg = lane & 3;
    int r0 = blockIdx.x * 128 + warp * 16 + g;   // rows for c0/c1
    int r1 = r0 + 8;                             // rows for c2/c3
    bool ok0 = r0 < N, ok1 = r1 < N;
    const int KS = K / 8;

    float acc[12][4];
    #pragma unroll
    for (int nt = 0; nt < 12; nt++)
        #pragma unroll
        for (int j = 0; j < 4; j++) acc[nt][j] = 0.f;

    const float* Ar0 = A + (size_t)r0 * K;
    const float* Ar1 = A + (size_t)r1 * K;
    const unsigned* wph = g_wp_hi + layer * 12288;
    const unsigned* wpl = g_wp_lo + layer * 12288;

    for (int ks = 0; ks < KS; ks++) {
        int k0 = ks * 8 + tg;
        // A frag m16k8: a0=(g,tg) a1=(g+8,tg) a2=(g,tg+4) a3=(g+8,tg+4)
        float v0 = ok0 ? Ar0[k0]     : 0.f;
        float v1 = ok1 ? Ar1[k0]     : 0.f;
        float v2 = ok0 ? Ar0[k0 + 4] : 0.f;
        float v3 = ok1 ? Ar1[k0 + 4] : 0.f;
        unsigned ah0, al0, ah1, al1, ah2, al2, ah3, al3;
        split_tf32(v0, ah0, al0);
        split_tf32(v1, ah1, al1);
        split_tf32(v2, ah2, al2);
        split_tf32(v3, ah3, al3);
        const unsigned* bh = wph + ks * 768 + lane * 2;
        const unsigned* bl = wpl + ks * 768 + lane * 2;
        #pragma unroll
        for (int nt = 0; nt < 12; nt++) {
            uint2 bhv = *(const uint2*)(bh + nt * 64);
            uint2 blv = *(const uint2*)(bl + nt * 64);
            mma_tf32(acc[nt], ah0, ah1, ah2, ah3, bhv.x, bhv.y);  // Ahi*Whi
            mma_tf32(acc[nt], ah0, ah1, ah2, ah3, blv.x, blv.y);  // Ahi*Wlo
            mma_tf32(acc[nt], al0, al1, al2, al3, bhv.x, bhv.y);  // Alo*Whi
        }
    }

    // epilogue: store h0 + fused es/ed (C frag identical to m16n8k16)
    float es0a = 0.f, es1a = 0.f, ed0a = 0.f, ed1a = 0.f;  // row r0 (heads 0/1)
    float es0b = 0.f, es1b = 0.f, ed0b = 0.f, ed1b = 0.f;  // row r1
    #pragma unroll
    for (int nt = 0; nt < 12; nt++) {
        int c = nt * 8 + tg * 2;
        float av0 = as[c], av1 = as[c + 1];
        float dv0 = ad[c], dv1 = ad[c + 1];
        float ea = av0 * acc[nt][0] + av1 * acc[nt][1];
        float da = dv0 * acc[nt][0] + dv1 * acc[nt][1];
        float eb = av0 * acc[nt][2] + av1 * acc[nt][3];
        float db = dv0 * acc[nt][2] + dv1 * acc[nt][3];
        if (H == 2 && nt >= 6) { es1a += ea; ed1a += da; es1b += eb; ed1b += db; }
        else                   { es0a += ea; ed0a += da; es0b += eb; ed0b += db; }
        if (ok0) *(float2*)(g_h0 + (size_t)r0 * 96 + c) = make_float2(acc[nt][0], acc[nt][1]);
        if (ok1) *(float2*)(g_h0 + (size_t)r1 * 96 + c) = make_float2(acc[nt][2], acc[nt][3]);
    }
    // reduce across the 4 lanes of the quad (consecutive lanes)
    #pragma unroll
    for (int o = 1; o < 4; o <<= 1) {
        es0a += __shfl_xor_sync(0xffffffffu, es0a, o);
        ed0a += __shfl_xor_sync(0xffffffffu, ed0a, o);
        es0b += __shfl_xor_sync(0xffffffffu, es0b, o);
        ed0b += __shfl_xor_sync(0xffffffffu, ed0b, o);
        if (H == 2) {
            es1a += __shfl_xor_sync(0xffffffffu, es1a, o);
            ed1a += __shfl_xor_sync(0xffffffffu, ed1a, o);
            es1b += __shfl_xor_sync(0xffffffffu, es1b, o);
            ed1b += __shfl_xor_sync(0xffffffffu, ed1b, o);
        }
    }
    if (tg == 0) {
        if (H == 2) {
            if (ok0) { g_es[r0 * 2] = es0a; g_es[r0 * 2 + 1] = es1a;
                       g_ed[r0 * 2] = ed0a; g_ed[r0 * 2 + 1] = ed1a; }
            if (ok1) { g_es[r1 * 2] = es0b; g_es[r1 * 2 + 1] = es1b;
                       g_ed[r1 * 2] = ed0b; g_ed[r1 * 2 + 1] = ed1b; }
        } else {
            if (ok0) { g_es[r0] = es0a; g_ed[r0] = ed0a; }
            if (ok1) { g_es[r1] = es0b; g_ed[r1] = ed0b; }
        }
    }
}

// ------------- segment softmax + weighted aggregation (warp/node) ----------
template <int H, bool LAST>
__global__ void agg_k(const float* __restrict__ bias,
                      const void* __restrict__ batch, int N) {
    int v = (blockIdx.x * blockDim.x + threadIdx.x) >> 5;
    int lane = threadIdx.x & 31;
    if (v >= N) return;
    int beg = g_begin[v];
    int deg = g_cnt[v];
    int end = beg + deg;

    float ed0 = g_ed[v * H];
    float ed1 = (H == 2) ? g_ed[v * 2 + 1] : 0.f;

    float inv0, inv1;
    float a0 = 0.f, a1 = 0.f, a2 = 0.f;
    int c0 = lane, c1 = lane + 32, c2 = lane + 64;

    if (deg <= 32) {
        int s = (lane < deg) ? g_csrc[beg + lane] : 0;
        float e0 = -3.4e38f, e1 = -3.4e38f;
        if (lane < deg) {
            e0 = g_es[s * H] + ed0;
            e0 = (e0 > 0.f) ? e0 : 0.2f * e0;
            if (H == 2) {
                e1 = g_es[s * 2 + 1] + ed1;
                e1 = (e1 > 0.f) ? e1 : 0.2f * e1;
            }
        }
        float m0 = e0, m1 = e1;
        #pragma unroll
        for (int o = 16; o; o >>= 1) {
            m0 = fmaxf(m0, __shfl_xor_sync(0xffffffffu, m0, o));
            if (H == 2) m1 = fmaxf(m1, __shfl_xor_sync(0xffffffffu, m1, o));
        }
        float p0 = (lane < deg) ? __expf(e0 - m0) : 0.f;
        float p1 = (H == 2 && lane < deg) ? __expf(e1 - m1) : 0.f;
        float s0 = p0, s1 = p1;
        #pragma unroll
        for (int o = 16; o; o >>= 1) {
            s0 += __shfl_xor_sync(0xffffffffu, s0, o);
            if (H == 2) s1 += __shfl_xor_sync(0xffffffffu, s1, o);
        }
        inv0 = 1.0f / s0;
        inv1 = (H == 2) ? 1.0f / s1 : inv0;

        for (int i = 0; i < deg; i++) {
            int si = __shfl_sync(0xffffffffu, s, i);
            float pi0 = __shfl_sync(0xffffffffu, p0, i);
            const float* hr = g_h0 + (size_t)si * 96;
            if (H == 2) {
                float pi1 = __shfl_sync(0xffffffffu, p1, i);
                a0 += pi0 * hr[c0];
                a1 += ((c1 < 48) ? pi0 : pi1) * hr[c1];
                a2 += pi1 * hr[c2];
            } else {
                a0 += pi0 * hr[c0];
                a1 += pi0 * hr[c1];
                a2 += pi0 * hr[c2];
            }
        }
    } else {
        float m0 = -3.4e38f, m1 = -3.4e38f;
        for (int i = beg + lane; i < end; i += 32) {
            int s = g_csrc[i];
            float e0 = g_es[s * H] + ed0;
            e0 = (e0 > 0.f) ? e0 : 0.2f * e0;
            g_ebuf[i * H] = e0;
            m0 = fmaxf(m0, e0);
            if (H == 2) {
                float e1 = g_es[s * 2 + 1] + ed1;
                e1 = (e1 > 0.f) ? e1 : 0.2f * e1;
                g_ebuf[i * 2 + 1] = e1;
                m1 = fmaxf(m1, e1);
            }
        }
        #pragma unroll
        for (int o = 16; o; o >>= 1) {
            m0 = fmaxf(m0, __shfl_xor_sync(0xffffffffu, m0, o));
            if (H == 2) m1 = fmaxf(m1, __shfl_xor_sync(0xffffffffu, m1, o));
        }
        float s0 = 0.f, s1 = 0.f;
        for (int i = beg + lane; i < end; i += 32) {
            float p0 = __expf(g_ebuf[i * H] - m0);
            g_ebuf[i * H] = p0;
            s0 += p0;
            if (H == 2) {
                float p1 = __expf(g_ebuf[i * 2 + 1] - m1);
                g_ebuf[i * 2 + 1] = p1;
                s1 += p1;
            }
        }
        #pragma unroll
        for (int o = 16; o; o >>= 1) {
            s0 += __shfl_xor_sync(0xffffffffu, s0, o);
            if (H == 2) s1 += __shfl_xor_sync(0xffffffffu, s1, o);
        }
        inv0 = 1.0f / s0;
        inv1 = (H == 2) ? 1.0f / s1 : inv0;

        for (int i = beg; i < end; i++) {
            int s = g_csrc[i];
            const float* hr = g_h0 + (size_t)s * 96;
            if (H == 2) {
                float p0 = g_ebuf[i * 2 + 0];
                float p1 = g_ebuf[i * 2 + 1];
                a0 += p0 * hr[c0];
                a1 += ((c1 < 48) ? p0 : p1) * hr[c1];
                a2 += p1 * hr[c2];
            } else {
                float p = g_ebuf[i];
                a0 += p * hr[c0];
                a1 += p * hr[c1];
                a2 += p * hr[c2];
            }
        }
    }

    float o0, o1, o2;
    if (H == 2) {
        o0 = a0 * inv0 + bias[c0];
        o1 = a1 * ((c1 < 48) ? inv0 : inv1) + bias[c1];
        o2 = a2 * inv1 + bias[c2];
    } else {
        o0 = a0 * inv0 + bias[c0];
        o1 = a1 * inv0 + bias[c1];
        o2 = a2 * inv0 + bias[c2];
    }
    o0 = fmaxf(o0, 0.f);
    o1 = fmaxf(o1, 0.f);
    o2 = fmaxf(o2, 0.f);

    if (LAST) {
        // fused global mean pool (sum part)
        int gb = load_idx(batch, v, g_is64_b);
        atomicAdd(&g_psum[gb * 96 + c0], o0);
        atomicAdd(&g_psum[gb * 96 + c1], o1);
        atomicAdd(&g_psum[gb * 96 + c2], o2);
        if (lane == 0) atomicAdd(&g_pcnt[gb], 1.0f);
    } else {
        float* orow = g_h1 + (size_t)v * 96;
        orow[c0] = o0;
        orow[c1] = o1;
        orow[c2] = o2;
    }
}

// ------------------------------- head -------------------------------------
__global__ void head_k(const float* __restrict__ Wc,
                       const float* __restrict__ bc,
                       float* __restrict__ out) {
    int g = (blockIdx.x * blockDim.x + threadIdx.x) >> 5;
    int lane = threadIdx.x & 31;
    if (g >= NGRAPH) return;
    float cnt = fmaxf(g_pcnt[g], 1.0f);
    float acc = 0.f;
    #pragma unroll
    for (int j = 0; j < 3; j++) {
        int c = lane + 32 * j;
        acc += (g_psum[g * 96 + c] / cnt) * Wc[c];
    }
    #pragma unroll
    for (int o = 16; o; o >>= 1)
        acc += __shfl_xor_sync(0xffffffffu, acc, o);
    if (lane == 0)
        out[g] = 1.0f / (1.0f + __expf(-(acc + bc[0])));
}

// ------------------------------- launch -----------------------------------
extern "C" void kernel_launch(void* const* d_in, const int* in_sizes, int n_in,
                              void* d_out, int out_size) {
    const float* x     = (const float*)d_in[0];
    const void*  eidx  = d_in[1];            // int32 or int64 (auto-detected)
    // d_in[2] edge_weight: ignored by GATConv (edge_dim=None)
    const void*  batch = d_in[3];
    const float* W1  = (const float*)d_in[4];
    const float* as1 = (const float*)d_in[5];
    const float* ad1 = (const float*)d_in[6];
    const float* b1  = (const float*)d_in[7];
    const float* W2  = (const float*)d_in[8];
    const float* as2 = (const float*)d_in[9];
    const float* ad2 = (const float*)d_in[10];
    const float* b2  = (const float*)d_in[11];
    const float* W3  = (const float*)d_in[12];
    const float* as3 = (const float*)d_in[13];
    const float* ad3 = (const float*)d_in[14];
    const float* b3  = (const float*)d_in[15];
    const float* W4  = (const float*)d_in[16];
    const float* as4 = (const float*)d_in[17];
    const float* ad4 = (const float*)d_in[18];
    const float* b4  = (const float*)d_in[19];
    const float* Wc  = (const float*)d_in[20];
    const float* bc  = (const float*)d_in[21];
    float* out = (float*)d_out;

    int N  = in_sizes[3];          // 50000
    int E  = in_sizes[2];          // 800000
    int ET = E + N;
    int nb = (N + 255) / 256;

    init_k<<<nb, 256>>>(eidx, batch, N);
    count_k<<<(ET + 255) / 256, 256>>>(eidx, E, N);
    scan_k<<<nb, 256>>>(N);
    fill_k<<<(ET + 255) / 256, 256>>>(eidx, E, N);
    wprep_k<<<52, 768>>>(W1, W2, W3, W4);

    int gb = (N + 127) / 128;
    int wgrid = (int)(((long long)N * 32 + 255) / 256);

    mma_gemm_attn_k<128, 2><<<gb, 256>>>(x, 1, 0, as1, ad1, N);
    agg_k<2, false><<<wgrid, 256>>>(b1, batch, N);
    mma_gemm_attn_k<96, 1><<<gb, 256>>>(nullptr, 0, 1, as2, ad2, N);
    agg_k<1, false><<<wgrid, 256>>>(b2, batch, N);
    mma_gemm_attn_k<96, 1><<<gb, 256>>>(nullptr, 0, 2, as3, ad3, N);
    agg_k<1, false><<<wgrid, 256>>>(b3, batch, N);
    mma_gemm_attn_k<96, 1><<<gb, 256>>>(nullptr, 0, 3, as4, ad4, N);
    agg_k<1, true><<<wgrid, 256>>>(b4, batch, N);

    head_k<<<2, 1024>>>(Wc, bc, out);
}

// round 12
// speedup vs baseline: 1.4569x; 1.0269x over previous
#include <cuda_runtime.h>

// ---------------------------------------------------------------------------
// GATSummarizer: 4-layer GAT + mean pool + sigmoid head.
// R6: overlap CSR-count with layer-1 GEMM (one fused launch, block-range
// dispatch), wprep fused into init, self-loops pre-counted, int4-vectorized
// edge reads. Core: tf32 3-term-split mma GEMM + fused attn epilogue,
// warp-per-node segment softmax aggregation, pool fused into last agg.
// ---------------------------------------------------------------------------

#define NMAX 50016
#define ETMAX 860032
#define NGRAPH 64

__device__ __align__(16) float g_h0[NMAX * 96];   // GEMM output (current h)
__device__ __align__(16) float g_h1[NMAX * 96];   // aggregated output
__device__ float g_es[NMAX * 2];
__device__ float g_ed[NMAX * 2];
__device__ float g_ebuf[ETMAX * 2];    // slow-path per-edge values
__device__ int   g_cnt[NMAX];
__device__ int   g_begin[NMAX];        // CSR segment start per node
__device__ int   g_cursor[NMAX];
__device__ int   g_csrc[ETMAX];
__device__ int   g_total;
__device__ float g_psum[NGRAPH * 96];
__device__ float g_pcnt[NGRAPH];
__device__ int   g_is64_e;
__device__ int   g_is64_b;
// pre-packed W fragments: [layer][ks<=16][nt=12][lane=32][2 regs], tf32 bits
__device__ unsigned g_wp_hi[4 * 16 * 12 * 32 * 2];
__device__ unsigned g_wp_lo[4 * 16 * 12 * 32 * 2];

// ---------------- tf32 split helpers ----------------
__device__ __forceinline__ void split_tf32(float v, unsigned& hi, unsigned& lo) {
    unsigned h;
    asm("cvt.rna.tf32.f32 %0, %1;" : "=r"(h) : "f"(v));
    float r = v - __uint_as_float(h);
    asm("cvt.rna.tf32.f32 %0, %1;" : "=r"(lo) : "f"(r));
    hi = h;
}

__device__ __forceinline__ void mma_tf32(float* d,
                                         unsigned a0, unsigned a1,
                                         unsigned a2, unsigned a3,
                                         unsigned b0, unsigned b1) {
    asm volatile(
        "mma.sync.aligned.m16n8k8.row.col.f32.tf32.tf32.f32 "
        "{%0,%1,%2,%3},{%4,%5,%6,%7},{%8,%9},{%0,%1,%2,%3};"
        : "+f"(d[0]), "+f"(d[1]), "+f"(d[2]), "+f"(d[3])
        : "r"(a0), "r"(a1), "r"(a2), "r"(a3), "r"(b0), "r"(b1));
}

__device__ __forceinline__ int load_idx(const void* p, long long i, int is64) {
    return is64 ? (int)((const long long*)p)[i] : ((const int*)p)[i];
}

// ------------- init (cnt=1 self-loop precount, pools, probe) + wprep -------
// grid: nbi blocks init (768 thr) + 52 blocks wprep.
__global__ void __launch_bounds__(768) initwprep_k(
    const void* __restrict__ eidx, const void* __restrict__ batch,
    const float* __restrict__ W1, const float* __restrict__ W2,
    const float* __restrict__ W3, const float* __restrict__ W4,
    int N, int nbi) {
    int bid = blockIdx.x;
    int tid = threadIdx.x;
    if (bid < nbi) {
        int i = bid * 768 + tid;
        if (i < N) g_cnt[i] = 1;          // self-loop pre-counted
        if (i < NGRAPH * 96) g_psum[i] = 0.f;
        if (i < NGRAPH) g_pcnt[i] = 0.f;
        if (bid == 0 && tid == 0) {
            g_total = 0;
            const int* e32 = (const int*)eidx;
            int all0 = 1;
            for (int j = 1; j < 64; j += 2) if (e32[j] != 0) all0 = 0;
            g_is64_e = all0;
            const int* b32 = (const int*)batch;
            int base = (N / 2) & ~1;
            all0 = 1;
            for (int j = 1; j < 64; j += 2) if (b32[base + j] != 0) all0 = 0;
            g_is64_b = all0;
        }
        return;
    }
    // ---- wprep: 52 blocks, ks-major across layers {16,12,12,12} ----
    int b = bid - nbi;
    int layer, ks;
    const float* W;
    if (b < 16)      { layer = 0; ks = b;      W = W1; }
    else if (b < 28) { layer = 1; ks = b - 16; W = W2; }
    else if (b < 40) { layer = 2; ks = b - 28; W = W3; }
    else             { layer = 3; ks = b - 40; W = W4; }
    int nt = tid / 64;
    int rem = tid % 64;
    int lane = rem >> 1;
    int reg = rem & 1;
    int tg = lane & 3, g = lane >> 2;
    int krow = ks * 8 + tg + reg * 4;
    int col = nt * 8 + g;
    float v = W[(size_t)krow * 96 + col];
    unsigned hi, lo;
    split_tf32(v, hi, lo);
    int idx = layer * 12288 + (ks * 12 + nt) * 64 + lane * 2 + reg;
    g_wp_hi[idx] = hi;
    g_wp_lo[idx] = lo;
}

// --------------- tensor-core GEMM + fused attention body -------------------
// C[N,96] = A[N,K] @ W[K,96] via m16n8k8 tf32 mma, hi/lo 3-term split.
// 256 threads = 8 warps; warp owns 16 rows x 96 cols. No __syncthreads.
template <int K, int H>
__device__ __forceinline__ void gemm_body(
    const float* __restrict__ A, int layer,
    const float* __restrict__ as, const float* __restrict__ ad,
    int N, int bid) {
    int lane = threadIdx.x & 31, warp = threadIdx.x >> 5;
    int g = lane >> 2, tg = lane & 3;
    int r0 = bid * 128 + warp * 16 + g;          // rows for c0/c1
    int r1 = r0 + 8;                             // rows for c2/c3
    bool ok0 = r0 < N, ok1 = r1 < N;
    const int KS = K / 8;

    float acc[12][4];
    #pragma unroll
    for (int nt = 0; nt < 12; nt++)
        #pragma unroll
        for (int j = 0; j < 4; j++) acc[nt][j] = 0.f;

    const float* Ar0 = A + (size_t)r0 * K;
    const float* Ar1 = A + (size_t)r1 * K;
    const unsigned* wph = g_wp_hi + layer * 12288;
    const unsigned* wpl = g_wp_lo + layer * 12288;

    for (int ks = 0; ks < KS; ks++) {
        int k0 = ks * 8 + tg;
        float v0 = ok0 ? Ar0[k0]     : 0.f;
        float v1 = ok1 ? Ar1[k0]     : 0.f;
        float v2 = ok0 ? Ar0[k0 + 4] : 0.f;
        float v3 = ok1 ? Ar1[k0 + 4] : 0.f;
        unsigned ah0, al0, ah1, al1, ah2, al2, ah3, al3;
        split_tf32(v0, ah0, al0);
        split_tf32(v1, ah1, al1);
        split_tf32(v2, ah2, al2);
        split_tf32(v3, ah3, al3);
        const unsigned* bh = wph + ks * 768 + lane * 2;
        const unsigned* bl = wpl + ks * 768 + lane * 2;
        #pragma unroll
        for (int nt = 0; nt < 12; nt++) {
            uint2 bhv = *(const uint2*)(bh + nt * 64);
            uint2 blv = *(const uint2*)(bl + nt * 64);
            mma_tf32(acc[nt], ah0, ah1, ah2, ah3, bhv.x, bhv.y);  // Ahi*Whi
            mma_tf32(acc[nt], ah0, ah1, ah2, ah3, blv.x, blv.y);  // Ahi*Wlo
            mma_tf32(acc[nt], al0, al1, al2, al3, bhv.x, bhv.y);  // Alo*Whi
        }
    }

    // epilogue: store h0 + fused es/ed
    float es0a = 0.f, es1a = 0.f, ed0a = 0.f, ed1a = 0.f;  // row r0 (heads 0/1)
    float es0b = 0.f, es1b = 0.f, ed0b = 0.f, ed1b = 0.f;  // row r1
    #pragma unroll
    for (int nt = 0; nt < 12; nt++) {
        int c = nt * 8 + tg * 2;
        float av0 = as[c], av1 = as[c + 1];
        float dv0 = ad[c], dv1 = ad[c + 1];
        float ea = av0 * acc[nt][0] + av1 * acc[nt][1];
        float da = dv0 * acc[nt][0] + dv1 * acc[nt][1];
        float eb = av0 * acc[nt][2] + av1 * acc[nt][3];
        float db = dv0 * acc[nt][2] + dv1 * acc[nt][3];
        if (H == 2 && nt >= 6) { es1a += ea; ed1a += da; es1b += eb; ed1b += db; }
        else                   { es0a += ea; ed0a += da; es0b += eb; ed0b += db; }
        if (ok0) *(float2*)(g_h0 + (size_t)r0 * 96 + c) = make_float2(acc[nt][0], acc[nt][1]);
        if (ok1) *(float2*)(g_h0 + (size_t)r1 * 96 + c) = make_float2(acc[nt][2], acc[nt][3]);
    }
    #pragma unroll
    for (int o = 1; o < 4; o <<= 1) {
        es0a += __shfl_xor_sync(0xffffffffu, es0a, o);
        ed0a += __shfl_xor_sync(0xffffffffu, ed0a, o);
        es0b += __shfl_xor_sync(0xffffffffu, es0b, o);
        ed0b += __shfl_xor_sync(0xffffffffu, ed0b, o);
        if (H == 2) {
            es1a += __shfl_xor_sync(0xffffffffu, es1a, o);
            ed1a += __shfl_xor_sync(0xffffffffu, ed1a, o);
            es1b += __shfl_xor_sync(0xffffffffu, es1b, o);
            ed1b += __shfl_xor_sync(0xffffffffu, ed1b, o);
        }
    }
    if (tg == 0) {
        if (H == 2) {
            if (ok0) { g_es[r0 * 2] = es0a; g_es[r0 * 2 + 1] = es1a;
                       g_ed[r0 * 2] = ed0a; g_ed[r0 * 2 + 1] = ed1a; }
            if (ok1) { g_es[r1 * 2] = es0b; g_es[r1 * 2 + 1] = es1b;
                       g_ed[r1 * 2] = ed0b; g_ed[r1 * 2 + 1] = ed1b; }
        } else {
            if (ok0) { g_es[r0] = es0a; g_ed[r0] = ed0a; }
            if (ok1) { g_es[r1] = es0b; g_ed[r1] = ed0b; }
        }
    }
}

// --------------- fused launch: layer-1 GEMM (blocks [0,gb)) + count --------
__global__ void __launch_bounds__(256) gemm1_count_k(
    const float* __restrict__ x, const float* __restrict__ as1,
    const float* __restrict__ ad1, const void* __restrict__ eidx,
    int E, int N, int gb) {
    int bid = blockIdx.x;
    if (bid < gb) {
        gemm_body<128, 2>(x, 0, as1, ad1, N, bid);
        return;
    }
    // count blocks: 4 edges per thread (self-loops pre-counted in init)
    int t = (bid - gb) * 256 + threadIdx.x;
    int base = t * 4;
    if (base >= E) return;
    int is64 = g_is64_e;
    if (!is64 && (E & 3) == 0) {
        const int4 d4 = *(const int4*)((const int*)eidx + E + base);
        atomicAdd(&g_cnt[d4.x], 1);
        atomicAdd(&g_cnt[d4.y], 1);
        atomicAdd(&g_cnt[d4.z], 1);
        atomicAdd(&g_cnt[d4.w], 1);
    } else {
        int lim = min(base + 4, E);
        for (int i = base; i < lim; i++)
            atomicAdd(&g_cnt[load_idx(eidx, (long long)E + i, is64)], 1);
    }
}

// single-pass scan: block-local scan + arrival-order block offset.
__global__ void scan_k(int N) {
    __shared__ int ws[8];
    __shared__ int sh_off;
    int tid = threadIdx.x;
    int i = blockIdx.x * 256 + tid;
    int lane = tid & 31, warp = tid >> 5;
    int v = (i < N) ? g_cnt[i] : 0;
    int x = v;
    #pragma unroll
    for (int o = 1; o < 32; o <<= 1) {
        int y = __shfl_up_sync(0xffffffffu, x, o);
        if (lane >= o) x += y;
    }
    if (lane == 31) ws[warp] = x;
    __syncthreads();
    if (tid == 0) {
        int run = 0;
        #pragma unroll
        for (int w = 0; w < 8; w++) { int t = ws[w]; ws[w] = run; run += t; }
    }
    __syncthreads();
    int incl = x + ws[warp];
    if (tid == 255) sh_off = atomicAdd(&g_total, incl);
    __syncthreads();
    if (i < N) {
        int beg = sh_off + incl - v;
        g_begin[i] = beg;
        g_cursor[i] = beg;
    }
}

// fill: vectorized edge scatter + self-loop blocks
__global__ void fillv_k(const void* __restrict__ eidx, int E, int N, int cbE) {
    int bid = blockIdx.x;
    int tid = threadIdx.x;
    if (bid < cbE) {
        int t = bid * 256 + tid;
        int base = t * 4;
        if (base >= E) return;
        int is64 = g_is64_e;
        if (!is64 && (E & 3) == 0) {
            const int4 s4 = *(const int4*)((const int*)eidx + base);
            const int4 d4 = *(const int4*)((const int*)eidx + E + base);
            int p0 = atomicAdd(&g_cursor[d4.x], 1); g_csrc[p0] = s4.x;
            int p1 = atomicAdd(&g_cursor[d4.y], 1); g_csrc[p1] = s4.y;
            int p2 = atomicAdd(&g_cursor[d4.z], 1); g_csrc[p2] = s4.z;
            int p3 = atomicAdd(&g_cursor[d4.w], 1); g_csrc[p3] = s4.w;
        } else {
            int lim = min(base + 4, E);
            for (int i = base; i < lim; i++) {
                int src = load_idx(eidx, i, is64);
                int dst = load_idx(eidx, (long long)E + i, is64);
                int pos = atomicAdd(&g_cursor[dst], 1);
                g_csrc[pos] = src;
            }
        }
        return;
    }
    // self-loop blocks
    int v = (bid - cbE) * 256 + tid;
    if (v >= N) return;
    int pos = atomicAdd(&g_cursor[v], 1);
    g_csrc[pos] = v;
}

// --------------- standalone GEMM (layers 2-4) ------------------------------
template <int K, int H>
__global__ void __launch_bounds__(256) mma_gemm_attn_k(
    int layer, const float* __restrict__ as, const float* __restrict__ ad,
    int N) {
    gemm_body<K, H>(g_h1, layer, as, ad, N, blockIdx.x);
}

// ------------- segment softmax + weighted aggregation (warp/node) ----------
template <int H, bool LAST>
__global__ void agg_k(const float* __restrict__ bias,
                      const void* __restrict__ batch, int N) {
    int v = (blockIdx.x * blockDim.x + threadIdx.x) >> 5;
    int lane = threadIdx.x & 31;
    if (v >= N) return;
    int beg = g_begin[v];
    int deg = g_cnt[v];
    int end = beg + deg;

    float ed0 = g_ed[v * H];
    float ed1 = (H == 2) ? g_ed[v * 2 + 1] : 0.f;

    float inv0, inv1;
    float a0 = 0.f, a1 = 0.f, a2 = 0.f;
    int c0 = lane, c1 = lane + 32, c2 = lane + 64;

    if (deg <= 32) {
        int s = (lane < deg) ? g_csrc[beg + lane] : 0;
        float e0 = -3.4e38f, e1 = -3.4e38f;
        if (lane < deg) {
            e0 = g_es[s * H] + ed0;
            e0 = (e0 > 0.f) ? e0 : 0.2f * e0;
            if (H == 2) {
                e1 = g_es[s * 2 + 1] + ed1;
                e1 = (e1 > 0.f) ? e1 : 0.2f * e1;
            }
        }
        float m0 = e0, m1 = e1;
        #pragma unroll
        for (int o = 16; o; o >>= 1) {
            m0 = fmaxf(m0, __shfl_xor_sync(0xffffffffu, m0, o));
            if (H == 2) m1 = fmaxf(m1, __shfl_xor_sync(0xffffffffu, m1, o));
        }
        float p0 = (lane < deg) ? __expf(e0 - m0) : 0.f;
        float p1 = (H == 2 && lane < deg) ? __expf(e1 - m1) : 0.f;
        float s0 = p0, s1 = p1;
        #pragma unroll
        for (int o = 16; o; o >>= 1) {
            s0 += __shfl_xor_sync(0xffffffffu, s0, o);
            if (H == 2) s1 += __shfl_xor_sync(0xffffffffu, s1, o);
        }
        inv0 = 1.0f / s0;
        inv1 = (H == 2) ? 1.0f / s1 : inv0;

        for (int i = 0; i < deg; i++) {
            int si = __shfl_sync(0xffffffffu, s, i);
            float pi0 = __shfl_sync(0xffffffffu, p0, i);
            const float* hr = g_h0 + (size_t)si * 96;
            if (H == 2) {
                float pi1 = __shfl_sync(0xffffffffu, p1, i);
                a0 += pi0 * hr[c0];
                a1 += ((c1 < 48) ? pi0 : pi1) * hr[c1];
                a2 += pi1 * hr[c2];
            } else {
                a0 += pi0 * hr[c0];
                a1 += pi0 * hr[c1];
                a2 += pi0 * hr[c2];
            }
        }
    } else {
        float m0 = -3.4e38f, m1 = -3.4e38f;
        for (int i = beg + lane; i < end; i += 32) {
            int s = g_csrc[i];
            float e0 = g_es[s * H] + ed0;
            e0 = (e0 > 0.f) ? e0 : 0.2f * e0;
            g_ebuf[i * H] = e0;
            m0 = fmaxf(m0, e0);
            if (H == 2) {
                float e1 = g_es[s * 2 + 1] + ed1;
                e1 = (e1 > 0.f) ? e1 : 0.2f * e1;
                g_ebuf[i * 2 + 1] = e1;
                m1 = fmaxf(m1, e1);
            }
        }
        #pragma unroll
        for (int o = 16; o; o >>= 1) {
            m0 = fmaxf(m0, __shfl_xor_sync(0xffffffffu, m0, o));
            if (H == 2) m1 = fmaxf(m1, __shfl_xor_sync(0xffffffffu, m1, o));
        }
        float s0 = 0.f, s1 = 0.f;
        for (int i = beg + lane; i < end; i += 32) {
            float p0 = __expf(g_ebuf[i * H] - m0);
            g_ebuf[i * H] = p0;
            s0 += p0;
            if (H == 2) {
                float p1 = __expf(g_ebuf[i * 2 + 1] - m1);
                g_ebuf[i * 2 + 1] = p1;
                s1 += p1;
            }
        }
        #pragma unroll
        for (int o = 16; o; o >>= 1) {
            s0 += __shfl_xor_sync(0xffffffffu, s0, o);
            if (H == 2) s1 += __shfl_xor_sync(0xffffffffu, s1, o);
        }
        inv0 = 1.0f / s0;
        inv1 = (H == 2) ? 1.0f / s1 : inv0;

        for (int i = beg; i < end; i++) {
            int s = g_csrc[i];
            const float* hr = g_h0 + (size_t)s * 96;
            if (H == 2) {
                float p0 = g_ebuf[i * 2 + 0];
                float p1 = g_ebuf[i * 2 + 1];
                a0 += p0 * hr[c0];
                a1 += ((c1 < 48) ? p0 : p1) * hr[c1];
                a2 += p1 * hr[c2];
            } else {
                float p = g_ebuf[i];
                a0 += p * hr[c0];
                a1 += p * hr[c1];
                a2 += p * hr[c2];
            }
        }
    }

    float o0, o1, o2;
    if (H == 2) {
        o0 = a0 * inv0 + bias[c0];
        o1 = a1 * ((c1 < 48) ? inv0 : inv1) + bias[c1];
        o2 = a2 * inv1 + bias[c2];
    } else {
        o0 = a0 * inv0 + bias[c0];
        o1 = a1 * inv0 + bias[c1];
        o2 = a2 * inv0 + bias[c2];
    }
    o0 = fmaxf(o0, 0.f);
    o1 = fmaxf(o1, 0.f);
    o2 = fmaxf(o2, 0.f);

    if (LAST) {
        int gb = load_idx(batch, v, g_is64_b);
        atomicAdd(&g_psum[gb * 96 + c0], o0);
        atomicAdd(&g_psum[gb * 96 + c1], o1);
        atomicAdd(&g_psum[gb * 96 + c2], o2);
        if (lane == 0) atomicAdd(&g_pcnt[gb], 1.0f);
    } else {
        float* orow = g_h1 + (size_t)v * 96;
        orow[c0] = o0;
        orow[c1] = o1;
        orow[c2] = o2;
    }
}

// ------------------------------- head -------------------------------------
__global__ void head_k(const float* __restrict__ Wc,
                       const float* __restrict__ bc,
                       float* __restrict__ out) {
    int g = (blockIdx.x * blockDim.x + threadIdx.x) >> 5;
    int lane = threadIdx.x & 31;
    if (g >= NGRAPH) return;
    float cnt = fmaxf(g_pcnt[g], 1.0f);
    float acc = 0.f;
    #pragma unroll
    for (int j = 0; j < 3; j++) {
        int c = lane + 32 * j;
        acc += (g_psum[g * 96 + c] / cnt) * Wc[c];
    }
    #pragma unroll
    for (int o = 16; o; o >>= 1)
        acc += __shfl_xor_sync(0xffffffffu, acc, o);
    if (lane == 0)
        out[g] = 1.0f / (1.0f + __expf(-(acc + bc[0])));
}

// ------------------------------- launch -----------------------------------
extern "C" void kernel_launch(void* const* d_in, const int* in_sizes, int n_in,
                              void* d_out, int out_size) {
    const float* x     = (const float*)d_in[0];
    const void*  eidx  = d_in[1];            // int32 or int64 (auto-detected)
    // d_in[2] edge_weight: ignored by GATConv (edge_dim=None)
    const void*  batch = d_in[3];
    const float* W1  = (const float*)d_in[4];
    const float* as1 = (const float*)d_in[5];
    const float* ad1 = (const float*)d_in[6];
    const float* b1  = (const float*)d_in[7];
    const float* W2  = (const float*)d_in[8];
    const float* as2 = (const float*)d_in[9];
    const float* ad2 = (const float*)d_in[10];
    const float* b2  = (const float*)d_in[11];
    const float* W3  = (const float*)d_in[12];
    const float* as3 = (const float*)d_in[13];
    const float* ad3 = (const float*)d_in[14];
    const float* b3  = (const float*)d_in[15];
    const float* W4  = (const float*)d_in[16];
    const float* as4 = (const float*)d_in[17];
    const float* ad4 = (const float*)d_in[18];
    const float* b4  = (const float*)d_in[19];
    const float* Wc  = (const float*)d_in[20];
    const float* bc  = (const float*)d_in[21];
    float* out = (float*)d_out;

    int N  = in_sizes[3];          // 50000
    int E  = in_sizes[2];          // 800000

    int nbi = (N + 767) / 768;                 // init blocks (covers psum too)
    int gb  = (N + 127) / 128;                 // gemm blocks
    int cbE = (E + 1023) / 1024;               // count/fill edge blocks (4/thr)
    int nbN = (N + 255) / 256;                 // per-node blocks
    int wgrid = (int)(((long long)N * 32 + 255) / 256);

    initwprep_k<<<nbi + 52, 768>>>(eidx, batch, W1, W2, W3, W4, N, nbi);
    gemm1_count_k<<<gb + cbE, 256>>>(x, as1, ad1, eidx, E, N, gb);
    scan_k<<<nbN, 256>>>(N);
    fillv_k<<<cbE + nbN, 256>>>(eidx, E, N, cbE);

    agg_k<2, false><<<wgrid, 256>>>(b1, batch, N);
    mma_gemm_attn_k<96, 1><<<gb, 256>>>(1, as2, ad2, N);
    agg_k<1, false><<<wgrid, 256>>>(b2, batch, N);
    mma_gemm_attn_k<96, 1><<<gb, 256>>>(2, as3, ad3, N);
    agg_k<1, false><<<wgrid, 256>>>(b3, batch, N);
    mma_gemm_attn_k<96, 1><<<gb, 256>>>(3, as4, ad4, N);
    agg_k<1, true><<<wgrid, 256>>>(b4, batch, N);

    head_k<<<2, 1024>>>(Wc, bc, out);
}